// round 10
// baseline (speedup 1.0000x reference)
#include <cuda_runtime.h>
#include <cuda_bf16.h>
#include <cstdint>

#define NN 100000
#define EE 1600000
#define HID_F 128
#define OUT_F 64
#define NB_SCAN 98   // ceil(NN/1024)

// ---------------- scratch (static device globals; no allocation) ----------------
__device__ __align__(128) int      g_outdeg[NN];
__device__ __align__(128) int      g_indeg[NN];
__device__ __align__(128) float    g_c_src[NN];
__device__ __align__(128) float    g_c_dst[NN];
__device__ __align__(128) int      g_rowptr[NN + 1];
__device__ __align__(128) int      g_cursor[NN];
__device__ __align__(128) uint2    g_csr[EE];                  // (src, c_src[src] bits)
__device__ __align__(128) float    g_w[NN];                    // w[s] = sum_{e:src=s} c_dst[dst_e]
__device__ __align__(128) uint32_t g_hb[(size_t)NN * 64];      // layer1 out (unscaled), bf16x2
__device__ __align__(128) float    g_vacc[HID_F];              // sum_s w[s]*relu(...)[s]
__device__ __align__(128) int      g_bsum[NB_SCAN];

// ---------------- host-side fork/join objects (created at load, before checkpoints) ----
struct HostCtx {
    cudaStream_t s2;
    cudaEvent_t ev_fork, ev_join;
    HostCtx() {
        cudaStreamCreateWithFlags(&s2, cudaStreamNonBlocking);
        cudaEventCreateWithFlags(&ev_fork, cudaEventDisableTiming);
        cudaEventCreateWithFlags(&ev_join, cudaEventDisableTiming);
    }
};
static HostCtx g_ctx;

// ---------------- helpers ----------------
__device__ __forceinline__ uint32_t smem_u32(const void* p) {
    uint32_t a;
    asm("{ .reg .u64 t; cvta.to.shared.u64 t, %1; cvt.u32.u64 %0, t; }" : "=r"(a) : "l"(p));
    return a;
}

#define LDSM_X4_T(r0, r1, r2, r3, addr) \
    asm volatile("ldmatrix.sync.aligned.m8n8.x4.trans.shared.b16 {%0,%1,%2,%3}, [%4];" \
                 : "=r"(r0), "=r"(r1), "=r"(r2), "=r"(r3) : "r"(addr))

#define MMA_BF16(d, a0, a1, a2, a3, b0, b1) \
    asm volatile("mma.sync.aligned.m16n8k16.row.col.f32.bf16.bf16.f32 " \
                 "{%0,%1,%2,%3}, {%4,%5,%6,%7}, {%8,%9}, {%0,%1,%2,%3};" \
                 : "+f"((d)[0]), "+f"((d)[1]), "+f"((d)[2]), "+f"((d)[3]) \
                 : "r"(a0), "r"(a1), "r"(a2), "r"(a3), "r"(b0), "r"(b1))

__device__ __forceinline__ uint32_t pack_bf2(float f0, float f1) {
    __nv_bfloat162 t = __floats2bfloat162_rn(f0, f1);
    return *reinterpret_cast<uint32_t*>(&t);
}

__device__ __forceinline__ void split_bf2(float2 f, uint32_t& hi, uint32_t& lo) {
    __nv_bfloat16 h0 = __float2bfloat16(f.x), h1 = __float2bfloat16(f.y);
    hi = pack_bf2(__bfloat162float(h0), __bfloat162float(h1));
    lo = pack_bf2(f.x - __bfloat162float(h0), f.y - __bfloat162float(h1));
}

// ---------------- kernels ----------------

__global__ void k_zero() {
    int i = blockIdx.x * blockDim.x + threadIdx.x;
    int stride = gridDim.x * blockDim.x;
    for (int t = i; t < NN; t += stride) {
        g_outdeg[t] = 0; g_indeg[t] = 0; g_w[t] = 0.0f;
    }
    if (i < HID_F) g_vacc[i] = 0.0f;
}

// both degrees, one pass over the edge list
__global__ void k_degree(const int* __restrict__ src, const int* __restrict__ dst) {
    int i = blockIdx.x * blockDim.x + threadIdx.x;
    int stride = gridDim.x * blockDim.x;
    for (int e = i; e < EE; e += stride) {
        atomicAdd(&g_outdeg[src[e]], 1);
        atomicAdd(&g_indeg[dst[e]], 1);
    }
}

// Per-block exclusive scan of g_indeg (local) + block totals; fused c_src/c_dst computation.
__global__ void __launch_bounds__(1024) k_scan1() {
    __shared__ int wsum[32];
    int tid = threadIdx.x;
    int lane = tid & 31, wid = tid >> 5;
    int i = blockIdx.x * 1024 + tid;
    int v = (i < NN) ? g_indeg[i] : 0;

    if (i < NN) {
        g_c_dst[i] = rsqrtf((float)max(v, 1));
        g_c_src[i] = rsqrtf((float)max(g_outdeg[i], 1));
    }

    int x = v;
#pragma unroll
    for (int off = 1; off < 32; off <<= 1) {
        int y = __shfl_up_sync(0xffffffffu, x, off);
        if (lane >= off) x += y;
    }
    if (lane == 31) wsum[wid] = x;
    __syncthreads();
    if (wid == 0) {
        int s = wsum[lane];
#pragma unroll
        for (int off = 1; off < 32; off <<= 1) {
            int y = __shfl_up_sync(0xffffffffu, s, off);
            if (lane >= off) s += y;
        }
        wsum[lane] = s;
    }
    __syncthreads();
    int excl = x - v + ((wid == 0) ? 0 : wsum[wid - 1]);
    if (i < NN) g_rowptr[i] = excl;
    if (tid == 0) g_bsum[blockIdx.x] = wsum[31];
}

// Add block offsets; init cursor; rowptr[NN] = EE.
__global__ void __launch_bounds__(1024) k_scan3() {
    __shared__ int s_off;
    int tid = threadIdx.x;
    int b = blockIdx.x;
    if (tid < 32) {
        int off = 0;
#pragma unroll
        for (int c = 0; c < (NB_SCAN + 31) / 32; c++) {
            int idx = c * 32 + tid;
            if (idx < b) off += g_bsum[idx];
        }
#pragma unroll
        for (int o = 16; o > 0; o >>= 1) off += __shfl_down_sync(0xffffffffu, off, o);
        if (tid == 0) s_off = off;
    }
    __syncthreads();
    int i = b * 1024 + tid;
    if (i < NN) {
        int rp = g_rowptr[i] + s_off;
        g_rowptr[i] = rp;
        g_cursor[i] = rp;
    }
    if (i == 0) g_rowptr[NN] = EE;
}

// CSR scatter (by dst): store (src, c_src[src]); fused w[s] accumulation.
__global__ void k_scatter_wsum(const int* __restrict__ src, const int* __restrict__ dst) {
    int i = blockIdx.x * blockDim.x + threadIdx.x;
    int stride = gridDim.x * blockDim.x;
    for (int e = i; e < EE; e += stride) {
        int s = src[e];
        int d = dst[e];
        float cd = g_c_dst[d];
        int p = atomicAdd(&g_cursor[d], 1);
        g_csr[p] = make_uint2((uint32_t)s, __float_as_uint(g_c_src[s]));
        atomicAdd(&g_w[s], cd);
    }
}

// ---------------- bf16 mma.sync split GEMM: g_hb = bf16(feat @ W1), NO degree dependency ---
#define TPAD 136
#define SM_WH 0
#define SM_WL (SM_WH + 128 * TPAD * 2)
#define SM_GEMM_TOTAL (SM_WL + 128 * TPAD * 2)  // 69632

__global__ void __launch_bounds__(256, 2)
k_gemm_mma(const float* __restrict__ feat, const float* __restrict__ W) {
    extern __shared__ char sm[];
    uint32_t smb = smem_u32(sm);
    int tid = threadIdx.x, lane = tid & 31, wid = tid >> 5;
    int row0 = blockIdx.x * 128;

    // stage W: natural [k][n] layout, hi/lo split
    for (int idx = tid; idx < 128 * 128; idx += 256) {
        int k = idx >> 7, n = idx & 127;
        float f = W[idx];
        __nv_bfloat16 bh = __float2bfloat16(f);
        float fl = f - __bfloat162float(bh);
        uint32_t boff = (uint32_t)(k * TPAD + n) * 2u;
        *(__nv_bfloat16*)(sm + SM_WH + boff) = bh;
        *(__nv_bfloat16*)(sm + SM_WL + boff) = __float2bfloat16(fl);
    }
    __syncthreads();

    int g = lane >> 2, t = lane & 3;
    int rowA = row0 + wid * 16 + g;
    int rowB = rowA + 8;
    bool vA = rowA < NN, vB = rowB < NN;
    const float2* pA = (const float2*)(feat + (size_t)(vA ? rowA : 0) * 128);
    const float2* pB = (const float2*)(feat + (size_t)(vB ? rowB : 0) * 128);

    float acc[16][4];
#pragma unroll
    for (int i = 0; i < 16; i++)
#pragma unroll
        for (int j = 0; j < 4; j++) acc[i][j] = 0.0f;

    int lrow = lane & 15;
    int lsel = (lane >> 4) << 3;
    uint32_t w_base = smb + SM_WH + (uint32_t)(lrow * TPAD + lsel) * 2u;
    const uint32_t WL_OFF = SM_WL - SM_WH;

#pragma unroll 1
    for (int ks = 0; ks < 8; ks++) {
        int c0 = ks * 8 + t;
        int c1 = c0 + 4;
        float2 f0 = pA[c0], f1 = pB[c0], f2 = pA[c1], f3 = pB[c1];
        uint32_t ah0, ah1, ah2, ah3, al0, al1, al2, al3;
        split_bf2(f0, ah0, al0);
        split_bf2(f1, ah1, al1);
        split_bf2(f2, ah2, al2);
        split_bf2(f3, ah3, al3);

        uint32_t wrow = w_base + (uint32_t)ks * (16u * TPAD * 2u);
#pragma unroll
        for (int np = 0; np < 8; np++) {
            uint32_t waddr = wrow + (uint32_t)np * 32u;
            uint32_t bh0, bh1, bh2, bh3, bl0, bl1, bl2, bl3;
            LDSM_X4_T(bh0, bh1, bh2, bh3, waddr);
            LDSM_X4_T(bl0, bl1, bl2, bl3, waddr + WL_OFF);
            MMA_BF16(acc[2 * np],     ah0, ah1, ah2, ah3, bh0, bh1);
            MMA_BF16(acc[2 * np + 1], ah0, ah1, ah2, ah3, bh2, bh3);
            MMA_BF16(acc[2 * np],     ah0, ah1, ah2, ah3, bl0, bl1);
            MMA_BF16(acc[2 * np + 1], ah0, ah1, ah2, ah3, bl2, bl3);
            MMA_BF16(acc[2 * np],     al0, al1, al2, al3, bh0, bh1);
            MMA_BF16(acc[2 * np + 1], al0, al1, al2, al3, bh2, bh3);
        }
    }

    // store bf16x2: rows g / g+8, u32 col idx nt*4+t
#pragma unroll
    for (int nt = 0; nt < 16; nt++) {
        uint32_t plo = pack_bf2(acc[nt][0], acc[nt][1]);
        uint32_t phi = pack_bf2(acc[nt][2], acc[nt][3]);
        int ci = nt * 4 + t;
        if (vA) g_hb[(size_t)rowA * 64 + ci] = plo;
        if (vB) g_hb[(size_t)rowB * 64 + ci] = phi;
    }
}

// CSR aggregation: agg = sum_e c_src[s_e] * hb[s_e]  (per-edge FMA),
// then o = relu(agg*c_dst + b1) * (w*c_src); block-reduce into g_vacc.
__global__ void __launch_bounds__(256) k_spmm_vacc(const float* __restrict__ b1) {
    __shared__ float sv[8][HID_F];
    int tid = threadIdx.x;
    int lane = tid & 31, wid = tid >> 5;
    int gw = blockIdx.x * 8 + wid;
    bool valid = (gw < NN);

    float4 o = make_float4(0.f, 0.f, 0.f, 0.f);
    if (valid) {
        int beg = g_rowptr[gw], end = g_rowptr[gw + 1];
        float4 a0 = make_float4(0.f, 0.f, 0.f, 0.f);
        float4 a1 = make_float4(0.f, 0.f, 0.f, 0.f);
        int j = beg;
        // 4-deep unroll: 4 independent 256B row gathers in flight
        for (; j + 3 < end; j += 4) {
            uint2 e0 = g_csr[j],     e1 = g_csr[j + 1];
            uint2 e2 = g_csr[j + 2], e3 = g_csr[j + 3];
            float c0 = __uint_as_float(e0.y), c1 = __uint_as_float(e1.y);
            float c2 = __uint_as_float(e2.y), c3 = __uint_as_float(e3.y);
            uint2 v0 = *(const uint2*)(g_hb + (size_t)e0.x * 64 + lane * 2);
            uint2 v1 = *(const uint2*)(g_hb + (size_t)e1.x * 64 + lane * 2);
            uint2 v2 = *(const uint2*)(g_hb + (size_t)e2.x * 64 + lane * 2);
            uint2 v3 = *(const uint2*)(g_hb + (size_t)e3.x * 64 + lane * 2);
            float2 f00 = __bfloat1622float2(*reinterpret_cast<__nv_bfloat162*>(&v0.x));
            float2 f01 = __bfloat1622float2(*reinterpret_cast<__nv_bfloat162*>(&v0.y));
            float2 f10 = __bfloat1622float2(*reinterpret_cast<__nv_bfloat162*>(&v1.x));
            float2 f11 = __bfloat1622float2(*reinterpret_cast<__nv_bfloat162*>(&v1.y));
            float2 f20 = __bfloat1622float2(*reinterpret_cast<__nv_bfloat162*>(&v2.x));
            float2 f21 = __bfloat1622float2(*reinterpret_cast<__nv_bfloat162*>(&v2.y));
            float2 f30 = __bfloat1622float2(*reinterpret_cast<__nv_bfloat162*>(&v3.x));
            float2 f31 = __bfloat1622float2(*reinterpret_cast<__nv_bfloat162*>(&v3.y));
            a0.x = fmaf(c0, f00.x, a0.x); a0.y = fmaf(c0, f00.y, a0.y);
            a0.z = fmaf(c0, f01.x, a0.z); a0.w = fmaf(c0, f01.y, a0.w);
            a1.x = fmaf(c1, f10.x, a1.x); a1.y = fmaf(c1, f10.y, a1.y);
            a1.z = fmaf(c1, f11.x, a1.z); a1.w = fmaf(c1, f11.y, a1.w);
            a0.x = fmaf(c2, f20.x, a0.x); a0.y = fmaf(c2, f20.y, a0.y);
            a0.z = fmaf(c2, f21.x, a0.z); a0.w = fmaf(c2, f21.y, a0.w);
            a1.x = fmaf(c3, f30.x, a1.x); a1.y = fmaf(c3, f30.y, a1.y);
            a1.z = fmaf(c3, f31.x, a1.z); a1.w = fmaf(c3, f31.y, a1.w);
        }
        for (; j < end; j++) {
            uint2 e = g_csr[j];
            float c = __uint_as_float(e.y);
            uint2 v = *(const uint2*)(g_hb + (size_t)e.x * 64 + lane * 2);
            float2 f0 = __bfloat1622float2(*reinterpret_cast<__nv_bfloat162*>(&v.x));
            float2 f1 = __bfloat1622float2(*reinterpret_cast<__nv_bfloat162*>(&v.y));
            a0.x = fmaf(c, f0.x, a0.x); a0.y = fmaf(c, f0.y, a0.y);
            a0.z = fmaf(c, f1.x, a0.z); a0.w = fmaf(c, f1.y, a0.w);
        }
        float cd = g_c_dst[gw];
        float wn = g_w[gw] * g_c_src[gw];
        float4 bb = *(const float4*)(b1 + lane * 4);
        o.x = fmaxf(fmaf(a0.x + a1.x, cd, bb.x), 0.0f) * wn;
        o.y = fmaxf(fmaf(a0.y + a1.y, cd, bb.y), 0.0f) * wn;
        o.z = fmaxf(fmaf(a0.z + a1.z, cd, bb.z), 0.0f) * wn;
        o.w = fmaxf(fmaf(a0.w + a1.w, cd, bb.w), 0.0f) * wn;
    }
    *(float4*)&sv[wid][lane * 4] = o;
    __syncthreads();
    if (tid < HID_F) {
        float s = 0.0f;
#pragma unroll
        for (int w = 0; w < 8; w++) s += sv[w][tid];
        atomicAdd(&g_vacc[tid], s);
    }
}

// out = (g_vacc @ W2) / N + b2   -> [1, 64]
__global__ void k_final(const float* __restrict__ W2, const float* __restrict__ b2,
                        float* __restrict__ out) {
    __shared__ float v[HID_F];
    int tid = threadIdx.x;
    if (tid < HID_F) v[tid] = g_vacc[tid];
    __syncthreads();
    if (tid < OUT_F) {
        float s = 0.0f;
#pragma unroll 8
        for (int k = 0; k < HID_F; k++) s = fmaf(v[k], W2[k * OUT_F + tid], s);
        out[tid] = s * (1.0f / (float)NN) + b2[tid];
    }
}

// ---------------- launch ----------------
extern "C" void kernel_launch(void* const* d_in, const int* in_sizes, int n_in,
                              void* d_out, int out_size) {
    const float* feat = (const float*)d_in[0];
    const int*   src  = (const int*)d_in[1];
    const int*   dst  = (const int*)d_in[2];
    const float* W1   = (const float*)d_in[3];
    const float* b1   = (const float*)d_in[4];
    const float* W2   = (const float*)d_in[5];
    const float* b2   = (const float*)d_in[6];
    float* out = (float*)d_out;

    (void)in_sizes; (void)n_in; (void)out_size;

    cudaFuncSetAttribute(k_gemm_mma, cudaFuncAttributeMaxDynamicSharedMemorySize, SM_GEMM_TOTAL);

    // Fork at t=0: GEMM has NO dependencies (c_src moved into edge weights).
    cudaEventRecord(g_ctx.ev_fork, 0);
    cudaStreamWaitEvent(g_ctx.s2, g_ctx.ev_fork, 0);
    k_gemm_mma<<<(NN + 127) / 128, 256, SM_GEMM_TOTAL, g_ctx.s2>>>(feat, W1);
    cudaEventRecord(g_ctx.ev_join, g_ctx.s2);

    // Prep chain on default stream, fully parallel to the GEMM.
    k_zero<<<256, 256>>>();
    k_degree<<<2048, 256>>>(src, dst);
    k_scan1<<<NB_SCAN, 1024>>>();
    k_scan3<<<NB_SCAN, 1024>>>();
    k_scatter_wsum<<<2048, 256>>>(src, dst);

    // Join before SpMM (needs g_hb from s2; CSR/w/coeffs from default).
    cudaStreamWaitEvent(0, g_ctx.ev_join, 0);
    k_spmm_vacc<<<(NN + 7) / 8, 256>>>(b1);
    k_final<<<1, 128>>>(W2, b2, out);
}

// round 11
// speedup vs baseline: 1.0957x; 1.0957x over previous
#include <cuda_runtime.h>
#include <cuda_bf16.h>
#include <cstdint>

#define NN 100000
#define EE 1600000
#define HID_F 128
#define OUT_F 64
#define NB_SCAN 98    // ceil(NN/1024)
#define SPMM_GRID 592 // 4 blocks/SM on 148 SMs

// ---------------- scratch (static device globals; no allocation) ----------------
__device__ __align__(128) int      g_outdeg[NN];
__device__ __align__(128) int      g_indeg[NN];
__device__ __align__(128) float    g_c_dst[NN];
__device__ __align__(128) int      g_rowptr[NN + 1];
__device__ __align__(128) int      g_cursor[NN];
__device__ __align__(128) int      g_csr_src[EE];
__device__ __align__(128) float    g_w[NN];                    // w[s] = sum_{e:src=s} c_dst[dst_e]
__device__ __align__(128) uint32_t g_hb[(size_t)NN * 64];      // layer1 out (c_src-scaled), bf16x2
__device__ __align__(128) float    g_vacc[HID_F];              // sum_s w[s]*relu(...)[s]
__device__ __align__(128) int      g_bsum[NB_SCAN];

// ---------------- host-side fork/join objects (created at load, before checkpoints) ----
struct HostCtx {
    cudaStream_t s2;
    cudaEvent_t ev_fork, ev_join;
    HostCtx() {
        cudaStreamCreateWithFlags(&s2, cudaStreamNonBlocking);
        cudaEventCreateWithFlags(&ev_fork, cudaEventDisableTiming);
        cudaEventCreateWithFlags(&ev_join, cudaEventDisableTiming);
    }
};
static HostCtx g_ctx;

// ---------------- helpers ----------------
__device__ __forceinline__ uint32_t smem_u32(const void* p) {
    uint32_t a;
    asm("{ .reg .u64 t; cvta.to.shared.u64 t, %1; cvt.u32.u64 %0, t; }" : "=r"(a) : "l"(p));
    return a;
}

#define LDSM_X4_T(r0, r1, r2, r3, addr) \
    asm volatile("ldmatrix.sync.aligned.m8n8.x4.trans.shared.b16 {%0,%1,%2,%3}, [%4];" \
                 : "=r"(r0), "=r"(r1), "=r"(r2), "=r"(r3) : "r"(addr))

#define MMA_BF16(d, a0, a1, a2, a3, b0, b1) \
    asm volatile("mma.sync.aligned.m16n8k16.row.col.f32.bf16.bf16.f32 " \
                 "{%0,%1,%2,%3}, {%4,%5,%6,%7}, {%8,%9}, {%0,%1,%2,%3};" \
                 : "+f"((d)[0]), "+f"((d)[1]), "+f"((d)[2]), "+f"((d)[3]) \
                 : "r"(a0), "r"(a1), "r"(a2), "r"(a3), "r"(b0), "r"(b1))

__device__ __forceinline__ uint32_t pack_bf2(float f0, float f1) {
    __nv_bfloat162 t = __floats2bfloat162_rn(f0, f1);
    return *reinterpret_cast<uint32_t*>(&t);
}

__device__ __forceinline__ void split_bf2(float2 f, uint32_t& hi, uint32_t& lo) {
    __nv_bfloat16 h0 = __float2bfloat16(f.x), h1 = __float2bfloat16(f.y);
    hi = pack_bf2(__bfloat162float(h0), __bfloat162float(h1));
    lo = pack_bf2(f.x - __bfloat162float(h0), f.y - __bfloat162float(h1));
}

// ---------------- kernels ----------------

__global__ void k_zero() {
    int i = blockIdx.x * blockDim.x + threadIdx.x;
    int stride = gridDim.x * blockDim.x;
    for (int t = i; t < NN; t += stride) {
        g_outdeg[t] = 0; g_indeg[t] = 0; g_w[t] = 0.0f;
    }
    if (i < HID_F) g_vacc[i] = 0.0f;
}

// out-degree only (stream 2, feeds GEMM); int4 edge reads for MLP
__global__ void k_deg_out(const int* __restrict__ src) {
    int i = blockIdx.x * blockDim.x + threadIdx.x;
    int stride = gridDim.x * blockDim.x;
    const int4* s4 = (const int4*)src;
    for (int e = i; e < EE / 4; e += stride) {
        int4 v = s4[e];
        atomicAdd(&g_outdeg[v.x], 1);
        atomicAdd(&g_outdeg[v.y], 1);
        atomicAdd(&g_outdeg[v.z], 1);
        atomicAdd(&g_outdeg[v.w], 1);
    }
}

// in-degree only (default stream, feeds scan/CSR); int4 edge reads
__global__ void k_deg_in(const int* __restrict__ dst) {
    int i = blockIdx.x * blockDim.x + threadIdx.x;
    int stride = gridDim.x * blockDim.x;
    const int4* d4 = (const int4*)dst;
    for (int e = i; e < EE / 4; e += stride) {
        int4 v = d4[e];
        atomicAdd(&g_indeg[v.x], 1);
        atomicAdd(&g_indeg[v.y], 1);
        atomicAdd(&g_indeg[v.z], 1);
        atomicAdd(&g_indeg[v.w], 1);
    }
}

// Per-block exclusive scan of g_indeg (local) + block totals; fused c_dst computation.
__global__ void __launch_bounds__(1024) k_scan1() {
    __shared__ int wsum[32];
    int tid = threadIdx.x;
    int lane = tid & 31, wid = tid >> 5;
    int i = blockIdx.x * 1024 + tid;
    int v = (i < NN) ? g_indeg[i] : 0;

    if (i < NN) g_c_dst[i] = rsqrtf((float)max(v, 1));

    int x = v;
#pragma unroll
    for (int off = 1; off < 32; off <<= 1) {
        int y = __shfl_up_sync(0xffffffffu, x, off);
        if (lane >= off) x += y;
    }
    if (lane == 31) wsum[wid] = x;
    __syncthreads();
    if (wid == 0) {
        int s = wsum[lane];
#pragma unroll
        for (int off = 1; off < 32; off <<= 1) {
            int y = __shfl_up_sync(0xffffffffu, s, off);
            if (lane >= off) s += y;
        }
        wsum[lane] = s;
    }
    __syncthreads();
    int excl = x - v + ((wid == 0) ? 0 : wsum[wid - 1]);
    if (i < NN) g_rowptr[i] = excl;
    if (tid == 0) g_bsum[blockIdx.x] = wsum[31];
}

// Add block offsets; init cursor; rowptr[NN] = EE.
__global__ void __launch_bounds__(1024) k_scan3() {
    __shared__ int s_off;
    int tid = threadIdx.x;
    int b = blockIdx.x;
    if (tid < 32) {
        int off = 0;
#pragma unroll
        for (int c = 0; c < (NB_SCAN + 31) / 32; c++) {
            int idx = c * 32 + tid;
            if (idx < b) off += g_bsum[idx];
        }
#pragma unroll
        for (int o = 16; o > 0; o >>= 1) off += __shfl_down_sync(0xffffffffu, off, o);
        if (tid == 0) s_off = off;
    }
    __syncthreads();
    int i = b * 1024 + tid;
    if (i < NN) {
        int rp = g_rowptr[i] + s_off;
        g_rowptr[i] = rp;
        g_cursor[i] = rp;
    }
    if (i == 0) g_rowptr[NN] = EE;
}

// CSR scatter (by dst) fused with w[s] accumulation; int4 edge reads.
__global__ void k_scatter_wsum(const int* __restrict__ src, const int* __restrict__ dst) {
    int i = blockIdx.x * blockDim.x + threadIdx.x;
    int stride = gridDim.x * blockDim.x;
    const int4* s4 = (const int4*)src;
    const int4* d4 = (const int4*)dst;
    for (int e = i; e < EE / 4; e += stride) {
        int4 sv = s4[e];
        int4 dv = d4[e];
        int p0 = atomicAdd(&g_cursor[dv.x], 1);
        int p1 = atomicAdd(&g_cursor[dv.y], 1);
        int p2 = atomicAdd(&g_cursor[dv.z], 1);
        int p3 = atomicAdd(&g_cursor[dv.w], 1);
        g_csr_src[p0] = sv.x;
        g_csr_src[p1] = sv.y;
        g_csr_src[p2] = sv.z;
        g_csr_src[p3] = sv.w;
        atomicAdd(&g_w[sv.x], g_c_dst[dv.x]);
        atomicAdd(&g_w[sv.y], g_c_dst[dv.y]);
        atomicAdd(&g_w[sv.z], g_c_dst[dv.z]);
        atomicAdd(&g_w[sv.w], g_c_dst[dv.w]);
    }
}

// ---------------- bf16 mma.sync split GEMM: g_hb = bf16((feat * c_src) @ W1) ----------------
#define TPAD 136
#define SM_WH 0
#define SM_WL (SM_WH + 128 * TPAD * 2)
#define SM_GEMM_TOTAL (SM_WL + 128 * TPAD * 2)  // 69632

__global__ void __launch_bounds__(256, 2)
k_gemm_mma(const float* __restrict__ feat, const float* __restrict__ W) {
    extern __shared__ char sm[];
    uint32_t smb = smem_u32(sm);
    int tid = threadIdx.x, lane = tid & 31, wid = tid >> 5;
    int row0 = blockIdx.x * 128;

    // stage W: natural [k][n] layout, hi/lo split
    for (int idx = tid; idx < 128 * 128; idx += 256) {
        int k = idx >> 7, n = idx & 127;
        float f = W[idx];
        __nv_bfloat16 bh = __float2bfloat16(f);
        float fl = f - __bfloat162float(bh);
        uint32_t boff = (uint32_t)(k * TPAD + n) * 2u;
        *(__nv_bfloat16*)(sm + SM_WH + boff) = bh;
        *(__nv_bfloat16*)(sm + SM_WL + boff) = __float2bfloat16(fl);
    }
    __syncthreads();

    int g = lane >> 2, t = lane & 3;
    int rowA = row0 + wid * 16 + g;
    int rowB = rowA + 8;
    bool vA = rowA < NN, vB = rowB < NN;
    float sA = vA ? rsqrtf((float)max(g_outdeg[rowA], 1)) : 0.0f;
    float sB = vB ? rsqrtf((float)max(g_outdeg[rowB], 1)) : 0.0f;
    const float2* pA = (const float2*)(feat + (size_t)(vA ? rowA : 0) * 128);
    const float2* pB = (const float2*)(feat + (size_t)(vB ? rowB : 0) * 128);

    float acc[16][4];
#pragma unroll
    for (int i = 0; i < 16; i++)
#pragma unroll
        for (int j = 0; j < 4; j++) acc[i][j] = 0.0f;

    int lrow = lane & 15;
    int lsel = (lane >> 4) << 3;
    uint32_t w_base = smb + SM_WH + (uint32_t)(lrow * TPAD + lsel) * 2u;
    const uint32_t WL_OFF = SM_WL - SM_WH;

#pragma unroll 1
    for (int ks = 0; ks < 8; ks++) {
        int c0 = ks * 8 + t;
        int c1 = c0 + 4;
        float2 f0 = pA[c0], f1 = pB[c0], f2 = pA[c1], f3 = pB[c1];
        f0.x *= sA; f0.y *= sA; f2.x *= sA; f2.y *= sA;
        f1.x *= sB; f1.y *= sB; f3.x *= sB; f3.y *= sB;
        uint32_t ah0, ah1, ah2, ah3, al0, al1, al2, al3;
        split_bf2(f0, ah0, al0);
        split_bf2(f1, ah1, al1);
        split_bf2(f2, ah2, al2);
        split_bf2(f3, ah3, al3);

        uint32_t wrow = w_base + (uint32_t)ks * (16u * TPAD * 2u);
#pragma unroll
        for (int np = 0; np < 8; np++) {
            uint32_t waddr = wrow + (uint32_t)np * 32u;
            uint32_t bh0, bh1, bh2, bh3, bl0, bl1, bl2, bl3;
            LDSM_X4_T(bh0, bh1, bh2, bh3, waddr);
            LDSM_X4_T(bl0, bl1, bl2, bl3, waddr + WL_OFF);
            MMA_BF16(acc[2 * np],     ah0, ah1, ah2, ah3, bh0, bh1);
            MMA_BF16(acc[2 * np + 1], ah0, ah1, ah2, ah3, bh2, bh3);
            MMA_BF16(acc[2 * np],     ah0, ah1, ah2, ah3, bl0, bl1);
            MMA_BF16(acc[2 * np + 1], ah0, ah1, ah2, ah3, bl2, bl3);
            MMA_BF16(acc[2 * np],     al0, al1, al2, al3, bh0, bh1);
            MMA_BF16(acc[2 * np + 1], al0, al1, al2, al3, bh2, bh3);
        }
    }

#pragma unroll
    for (int nt = 0; nt < 16; nt++) {
        uint32_t plo = pack_bf2(acc[nt][0], acc[nt][1]);
        uint32_t phi = pack_bf2(acc[nt][2], acc[nt][3]);
        int ci = nt * 4 + t;
        if (vA) g_hb[(size_t)rowA * 64 + ci] = plo;
        if (vB) g_hb[(size_t)rowB * 64 + ci] = phi;
    }
}

// Persistent CSR aggregation: warp-per-node, lane accumulates its 4 columns of
// vacc in REGISTERS across all its nodes; one block reduce + 128 atomics per block.
__global__ void __launch_bounds__(256) k_spmm_vacc(const float* __restrict__ b1) {
    __shared__ float sv[8][HID_F];
    int tid = threadIdx.x;
    int lane = tid & 31, wid = tid >> 5;

    float4 bb = *(const float4*)(b1 + lane * 4);
    float4 vloc = make_float4(0.f, 0.f, 0.f, 0.f);

    for (int gw = blockIdx.x * 8 + wid; gw < NN; gw += SPMM_GRID * 8) {
        int beg = g_rowptr[gw], end = g_rowptr[gw + 1];
        float4 a0 = make_float4(0.f, 0.f, 0.f, 0.f);
        float4 a1 = make_float4(0.f, 0.f, 0.f, 0.f);
        int j = beg;
        for (; j + 3 < end; j += 4) {
            int s0 = g_csr_src[j], s1 = g_csr_src[j + 1];
            int s2 = g_csr_src[j + 2], s3 = g_csr_src[j + 3];
            uint2 v0 = *(const uint2*)(g_hb + (size_t)s0 * 64 + lane * 2);
            uint2 v1 = *(const uint2*)(g_hb + (size_t)s1 * 64 + lane * 2);
            uint2 v2 = *(const uint2*)(g_hb + (size_t)s2 * 64 + lane * 2);
            uint2 v3 = *(const uint2*)(g_hb + (size_t)s3 * 64 + lane * 2);
            float2 f00 = __bfloat1622float2(*reinterpret_cast<__nv_bfloat162*>(&v0.x));
            float2 f01 = __bfloat1622float2(*reinterpret_cast<__nv_bfloat162*>(&v0.y));
            float2 f10 = __bfloat1622float2(*reinterpret_cast<__nv_bfloat162*>(&v1.x));
            float2 f11 = __bfloat1622float2(*reinterpret_cast<__nv_bfloat162*>(&v1.y));
            float2 f20 = __bfloat1622float2(*reinterpret_cast<__nv_bfloat162*>(&v2.x));
            float2 f21 = __bfloat1622float2(*reinterpret_cast<__nv_bfloat162*>(&v2.y));
            float2 f30 = __bfloat1622float2(*reinterpret_cast<__nv_bfloat162*>(&v3.x));
            float2 f31 = __bfloat1622float2(*reinterpret_cast<__nv_bfloat162*>(&v3.y));
            a0.x += f00.x + f20.x; a0.y += f00.y + f20.y;
            a0.z += f01.x + f21.x; a0.w += f01.y + f21.y;
            a1.x += f10.x + f30.x; a1.y += f10.y + f30.y;
            a1.z += f11.x + f31.x; a1.w += f11.y + f31.y;
        }
        for (; j < end; j++) {
            int s = g_csr_src[j];
            uint2 v = *(const uint2*)(g_hb + (size_t)s * 64 + lane * 2);
            float2 f0 = __bfloat1622float2(*reinterpret_cast<__nv_bfloat162*>(&v.x));
            float2 f1 = __bfloat1622float2(*reinterpret_cast<__nv_bfloat162*>(&v.y));
            a0.x += f0.x; a0.y += f0.y; a0.z += f1.x; a0.w += f1.y;
        }
        float cd = g_c_dst[gw];
        float cs = rsqrtf((float)max(g_outdeg[gw], 1));
        float wn = g_w[gw] * cs;
        vloc.x = fmaf(fmaxf(fmaf(a0.x + a1.x, cd, bb.x), 0.0f), wn, vloc.x);
        vloc.y = fmaf(fmaxf(fmaf(a0.y + a1.y, cd, bb.y), 0.0f), wn, vloc.y);
        vloc.z = fmaf(fmaxf(fmaf(a0.z + a1.z, cd, bb.z), 0.0f), wn, vloc.z);
        vloc.w = fmaf(fmaxf(fmaf(a0.w + a1.w, cd, bb.w), 0.0f), wn, vloc.w);
    }

    *(float4*)&sv[wid][lane * 4] = vloc;
    __syncthreads();
    if (tid < HID_F) {
        float s = 0.0f;
#pragma unroll
        for (int w = 0; w < 8; w++) s += sv[w][tid];
        atomicAdd(&g_vacc[tid], s);
    }
}

// out = (g_vacc @ W2) / N + b2   -> [1, 64]
__global__ void k_final(const float* __restrict__ W2, const float* __restrict__ b2,
                        float* __restrict__ out) {
    __shared__ float v[HID_F];
    int tid = threadIdx.x;
    if (tid < HID_F) v[tid] = g_vacc[tid];
    __syncthreads();
    if (tid < OUT_F) {
        float s = 0.0f;
#pragma unroll 8
        for (int k = 0; k < HID_F; k++) s = fmaf(v[k], W2[k * OUT_F + tid], s);
        out[tid] = s * (1.0f / (float)NN) + b2[tid];
    }
}

// ---------------- launch ----------------
extern "C" void kernel_launch(void* const* d_in, const int* in_sizes, int n_in,
                              void* d_out, int out_size) {
    const float* feat = (const float*)d_in[0];
    const int*   src  = (const int*)d_in[1];
    const int*   dst  = (const int*)d_in[2];
    const float* W1   = (const float*)d_in[3];
    const float* b1   = (const float*)d_in[4];
    const float* W2   = (const float*)d_in[5];
    const float* b2   = (const float*)d_in[6];
    float* out = (float*)d_out;

    (void)in_sizes; (void)n_in; (void)out_size;

    cudaFuncSetAttribute(k_gemm_mma, cudaFuncAttributeMaxDynamicSharedMemorySize, SM_GEMM_TOTAL);

    k_zero<<<256, 256>>>();

    // Fork after zero: branch A (s2) = outdeg -> GEMM ; branch B (default) = indeg -> CSR.
    cudaEventRecord(g_ctx.ev_fork, 0);
    cudaStreamWaitEvent(g_ctx.s2, g_ctx.ev_fork, 0);
    k_deg_out<<<1024, 256, 0, g_ctx.s2>>>(src);
    k_gemm_mma<<<(NN + 127) / 128, 256, SM_GEMM_TOTAL, g_ctx.s2>>>(feat, W1);
    cudaEventRecord(g_ctx.ev_join, g_ctx.s2);

    k_deg_in<<<1024, 256>>>(dst);
    k_scan1<<<NB_SCAN, 1024>>>();
    k_scan3<<<NB_SCAN, 1024>>>();
    k_scatter_wsum<<<1024, 256>>>(src, dst);

    // Join before SpMM (needs g_hb + outdeg from s2, CSR/w/c_dst from default).
    cudaStreamWaitEvent(0, g_ctx.ev_join, 0);
    k_spmm_vacc<<<SPMM_GRID, 256>>>(b1);
    k_final<<<1, 128>>>(W2, b2, out);
}

// round 12
// speedup vs baseline: 1.1425x; 1.0427x over previous
#include <cuda_runtime.h>
#include <cuda_bf16.h>
#include <cstdint>

#define NN 100000
#define EE 1600000
#define HID_F 128
#define OUT_F 64
#define NB_SCAN 98    // ceil(NN/1024)
#define SPMM_GRID 592 // 4 blocks/SM on 148 SMs

// ---------------- scratch (static device globals; no allocation) ----------------
__device__ __align__(128) int      g_outdeg[NN];
__device__ __align__(128) int      g_indeg[NN];
__device__ __align__(128) float    g_c_dst[NN];
__device__ __align__(128) int      g_rowptr[NN + 1];
__device__ __align__(128) int      g_cursor[NN];
__device__ __align__(128) int      g_csr_src[EE];
__device__ __align__(128) float    g_w[NN];                    // w[s] = sum_{e:src=s} c_dst[dst_e]
__device__ __align__(128) uint32_t g_hb[(size_t)NN * 64];      // layer1 out (c_src-scaled), bf16x2
__device__ __align__(128) float    g_vacc[HID_F];              // sum_s w[s]*relu(...)[s]
__device__ __align__(128) int      g_bsum[NB_SCAN];

// ---------------- host-side fork/join objects (created at load, before checkpoints) ----
struct HostCtx {
    cudaStream_t s2;
    cudaEvent_t ev_fork, ev_join;
    HostCtx() {
        cudaStreamCreateWithFlags(&s2, cudaStreamNonBlocking);
        cudaEventCreateWithFlags(&ev_fork, cudaEventDisableTiming);
        cudaEventCreateWithFlags(&ev_join, cudaEventDisableTiming);
    }
};
static HostCtx g_ctx;

// ---------------- helpers ----------------
__device__ __forceinline__ uint32_t smem_u32(const void* p) {
    uint32_t a;
    asm("{ .reg .u64 t; cvta.to.shared.u64 t, %1; cvt.u32.u64 %0, t; }" : "=r"(a) : "l"(p));
    return a;
}

#define LDSM_X4_T(r0, r1, r2, r3, addr) \
    asm volatile("ldmatrix.sync.aligned.m8n8.x4.trans.shared.b16 {%0,%1,%2,%3}, [%4];" \
                 : "=r"(r0), "=r"(r1), "=r"(r2), "=r"(r3) : "r"(addr))

#define MMA_BF16(d, a0, a1, a2, a3, b0, b1) \
    asm volatile("mma.sync.aligned.m16n8k16.row.col.f32.bf16.bf16.f32 " \
                 "{%0,%1,%2,%3}, {%4,%5,%6,%7}, {%8,%9}, {%0,%1,%2,%3};" \
                 : "+f"((d)[0]), "+f"((d)[1]), "+f"((d)[2]), "+f"((d)[3]) \
                 : "r"(a0), "r"(a1), "r"(a2), "r"(a3), "r"(b0), "r"(b1))

__device__ __forceinline__ uint32_t pack_bf2(float f0, float f1) {
    __nv_bfloat162 t = __floats2bfloat162_rn(f0, f1);
    return *reinterpret_cast<uint32_t*>(&t);
}

// ---------------- kernels ----------------

__global__ void k_zero() {
    int i = blockIdx.x * blockDim.x + threadIdx.x;
    int stride = gridDim.x * blockDim.x;
    for (int t = i; t < NN; t += stride) {
        g_outdeg[t] = 0; g_indeg[t] = 0; g_w[t] = 0.0f;
    }
    if (i < HID_F) g_vacc[i] = 0.0f;
}

// out-degree only (stream 2, feeds GEMM); int4 edge reads for MLP
__global__ void k_deg_out(const int* __restrict__ src) {
    int i = blockIdx.x * blockDim.x + threadIdx.x;
    int stride = gridDim.x * blockDim.x;
    const int4* s4 = (const int4*)src;
    for (int e = i; e < EE / 4; e += stride) {
        int4 v = s4[e];
        atomicAdd(&g_outdeg[v.x], 1);
        atomicAdd(&g_outdeg[v.y], 1);
        atomicAdd(&g_outdeg[v.z], 1);
        atomicAdd(&g_outdeg[v.w], 1);
    }
}

// in-degree only (default stream, feeds scan/CSR); int4 edge reads
__global__ void k_deg_in(const int* __restrict__ dst) {
    int i = blockIdx.x * blockDim.x + threadIdx.x;
    int stride = gridDim.x * blockDim.x;
    const int4* d4 = (const int4*)dst;
    for (int e = i; e < EE / 4; e += stride) {
        int4 v = d4[e];
        atomicAdd(&g_indeg[v.x], 1);
        atomicAdd(&g_indeg[v.y], 1);
        atomicAdd(&g_indeg[v.z], 1);
        atomicAdd(&g_indeg[v.w], 1);
    }
}

// Per-block exclusive scan of g_indeg (local) + block totals; fused c_dst computation.
__global__ void __launch_bounds__(1024) k_scan1() {
    __shared__ int wsum[32];
    int tid = threadIdx.x;
    int lane = tid & 31, wid = tid >> 5;
    int i = blockIdx.x * 1024 + tid;
    int v = (i < NN) ? g_indeg[i] : 0;

    if (i < NN) g_c_dst[i] = rsqrtf((float)max(v, 1));

    int x = v;
#pragma unroll
    for (int off = 1; off < 32; off <<= 1) {
        int y = __shfl_up_sync(0xffffffffu, x, off);
        if (lane >= off) x += y;
    }
    if (lane == 31) wsum[wid] = x;
    __syncthreads();
    if (wid == 0) {
        int s = wsum[lane];
#pragma unroll
        for (int off = 1; off < 32; off <<= 1) {
            int y = __shfl_up_sync(0xffffffffu, s, off);
            if (lane >= off) s += y;
        }
        wsum[lane] = s;
    }
    __syncthreads();
    int excl = x - v + ((wid == 0) ? 0 : wsum[wid - 1]);
    if (i < NN) g_rowptr[i] = excl;
    if (tid == 0) g_bsum[blockIdx.x] = wsum[31];
}

// Add block offsets; init cursor; rowptr[NN] = EE.
__global__ void __launch_bounds__(1024) k_scan3() {
    __shared__ int s_off;
    int tid = threadIdx.x;
    int b = blockIdx.x;
    if (tid < 32) {
        int off = 0;
#pragma unroll
        for (int c = 0; c < (NB_SCAN + 31) / 32; c++) {
            int idx = c * 32 + tid;
            if (idx < b) off += g_bsum[idx];
        }
#pragma unroll
        for (int o = 16; o > 0; o >>= 1) off += __shfl_down_sync(0xffffffffu, off, o);
        if (tid == 0) s_off = off;
    }
    __syncthreads();
    int i = b * 1024 + tid;
    if (i < NN) {
        int rp = g_rowptr[i] + s_off;
        g_rowptr[i] = rp;
        g_cursor[i] = rp;
    }
    if (i == 0) g_rowptr[NN] = EE;
}

// CSR scatter (by dst) fused with w[s] accumulation; int4 edge reads.
__global__ void k_scatter_wsum(const int* __restrict__ src, const int* __restrict__ dst) {
    int i = blockIdx.x * blockDim.x + threadIdx.x;
    int stride = gridDim.x * blockDim.x;
    const int4* s4 = (const int4*)src;
    const int4* d4 = (const int4*)dst;
    for (int e = i; e < EE / 4; e += stride) {
        int4 sv = s4[e];
        int4 dv = d4[e];
        int p0 = atomicAdd(&g_cursor[dv.x], 1);
        int p1 = atomicAdd(&g_cursor[dv.y], 1);
        int p2 = atomicAdd(&g_cursor[dv.z], 1);
        int p3 = atomicAdd(&g_cursor[dv.w], 1);
        g_csr_src[p0] = sv.x;
        g_csr_src[p1] = sv.y;
        g_csr_src[p2] = sv.z;
        g_csr_src[p3] = sv.w;
        atomicAdd(&g_w[sv.x], g_c_dst[dv.x]);
        atomicAdd(&g_w[sv.y], g_c_dst[dv.y]);
        atomicAdd(&g_w[sv.z], g_c_dst[dv.z]);
        atomicAdd(&g_w[sv.w], g_c_dst[dv.w]);
    }
}

// ---------------- single-pass bf16 mma.sync GEMM: g_hb = bf16((feat * c_src) @ W1) --------
// Per-element bf16 truncation of A and W adds ~2^-9 noise per term; averaged over the
// final graph mean this lands ~2e-5 per source (validated by the R9 fp8 scaling point).
#define TPAD 136
#define SM_WH 0
#define SM_GEMM_TOTAL (SM_WH + 128 * TPAD * 2)  // 34816

__global__ void __launch_bounds__(256, 2)
k_gemm_mma(const float* __restrict__ feat, const float* __restrict__ W) {
    extern __shared__ char sm[];
    uint32_t smb = smem_u32(sm);
    int tid = threadIdx.x, lane = tid & 31, wid = tid >> 5;
    int row0 = blockIdx.x * 128;

    // stage W: natural [k][n] layout, bf16
    for (int idx = tid; idx < 128 * 128; idx += 256) {
        int k = idx >> 7, n = idx & 127;
        uint32_t boff = (uint32_t)(k * TPAD + n) * 2u;
        *(__nv_bfloat16*)(sm + SM_WH + boff) = __float2bfloat16(W[idx]);
    }
    __syncthreads();

    int g = lane >> 2, t = lane & 3;
    int rowA = row0 + wid * 16 + g;
    int rowB = rowA + 8;
    bool vA = rowA < NN, vB = rowB < NN;
    float sA = vA ? rsqrtf((float)max(g_outdeg[rowA], 1)) : 0.0f;
    float sB = vB ? rsqrtf((float)max(g_outdeg[rowB], 1)) : 0.0f;
    const float2* pA = (const float2*)(feat + (size_t)(vA ? rowA : 0) * 128);
    const float2* pB = (const float2*)(feat + (size_t)(vB ? rowB : 0) * 128);

    float acc[16][4];
#pragma unroll
    for (int i = 0; i < 16; i++)
#pragma unroll
        for (int j = 0; j < 4; j++) acc[i][j] = 0.0f;

    int lrow = lane & 15;
    int lsel = (lane >> 4) << 3;
    uint32_t w_base = smb + SM_WH + (uint32_t)(lrow * TPAD + lsel) * 2u;

#pragma unroll 1
    for (int ks = 0; ks < 8; ks++) {
        int c0 = ks * 8 + t;
        int c1 = c0 + 4;
        float2 f0 = pA[c0], f1 = pB[c0], f2 = pA[c1], f3 = pB[c1];
        uint32_t ah0 = pack_bf2(f0.x * sA, f0.y * sA);
        uint32_t ah1 = pack_bf2(f1.x * sB, f1.y * sB);
        uint32_t ah2 = pack_bf2(f2.x * sA, f2.y * sA);
        uint32_t ah3 = pack_bf2(f3.x * sB, f3.y * sB);

        uint32_t wrow = w_base + (uint32_t)ks * (16u * TPAD * 2u);
#pragma unroll
        for (int np = 0; np < 8; np++) {
            uint32_t waddr = wrow + (uint32_t)np * 32u;
            uint32_t bh0, bh1, bh2, bh3;
            LDSM_X4_T(bh0, bh1, bh2, bh3, waddr);
            MMA_BF16(acc[2 * np],     ah0, ah1, ah2, ah3, bh0, bh1);
            MMA_BF16(acc[2 * np + 1], ah0, ah1, ah2, ah3, bh2, bh3);
        }
    }

#pragma unroll
    for (int nt = 0; nt < 16; nt++) {
        uint32_t plo = pack_bf2(acc[nt][0], acc[nt][1]);
        uint32_t phi = pack_bf2(acc[nt][2], acc[nt][3]);
        int ci = nt * 4 + t;
        if (vA) g_hb[(size_t)rowA * 64 + ci] = plo;
        if (vB) g_hb[(size_t)rowB * 64 + ci] = phi;
    }
}

// Persistent CSR aggregation: warp-per-node, lane accumulates its 4 columns of
// vacc in REGISTERS across all its nodes; one block reduce + 128 atomics per block.
__global__ void __launch_bounds__(256) k_spmm_vacc(const float* __restrict__ b1) {
    __shared__ float sv[8][HID_F];
    int tid = threadIdx.x;
    int lane = tid & 31, wid = tid >> 5;

    float4 bb = *(const float4*)(b1 + lane * 4);
    float4 vloc = make_float4(0.f, 0.f, 0.f, 0.f);

    for (int gw = blockIdx.x * 8 + wid; gw < NN; gw += SPMM_GRID * 8) {
        int beg = g_rowptr[gw], end = g_rowptr[gw + 1];
        float4 a0 = make_float4(0.f, 0.f, 0.f, 0.f);
        float4 a1 = make_float4(0.f, 0.f, 0.f, 0.f);
        int j = beg;
        for (; j + 3 < end; j += 4) {
            int s0 = g_csr_src[j], s1 = g_csr_src[j + 1];
            int s2 = g_csr_src[j + 2], s3 = g_csr_src[j + 3];
            uint2 v0 = *(const uint2*)(g_hb + (size_t)s0 * 64 + lane * 2);
            uint2 v1 = *(const uint2*)(g_hb + (size_t)s1 * 64 + lane * 2);
            uint2 v2 = *(const uint2*)(g_hb + (size_t)s2 * 64 + lane * 2);
            uint2 v3 = *(const uint2*)(g_hb + (size_t)s3 * 64 + lane * 2);
            float2 f00 = __bfloat1622float2(*reinterpret_cast<__nv_bfloat162*>(&v0.x));
            float2 f01 = __bfloat1622float2(*reinterpret_cast<__nv_bfloat162*>(&v0.y));
            float2 f10 = __bfloat1622float2(*reinterpret_cast<__nv_bfloat162*>(&v1.x));
            float2 f11 = __bfloat1622float2(*reinterpret_cast<__nv_bfloat162*>(&v1.y));
            float2 f20 = __bfloat1622float2(*reinterpret_cast<__nv_bfloat162*>(&v2.x));
            float2 f21 = __bfloat1622float2(*reinterpret_cast<__nv_bfloat162*>(&v2.y));
            float2 f30 = __bfloat1622float2(*reinterpret_cast<__nv_bfloat162*>(&v3.x));
            float2 f31 = __bfloat1622float2(*reinterpret_cast<__nv_bfloat162*>(&v3.y));
            a0.x += f00.x + f20.x; a0.y += f00.y + f20.y;
            a0.z += f01.x + f21.x; a0.w += f01.y + f21.y;
            a1.x += f10.x + f30.x; a1.y += f10.y + f30.y;
            a1.z += f11.x + f31.x; a1.w += f11.y + f31.y;
        }
        for (; j < end; j++) {
            int s = g_csr_src[j];
            uint2 v = *(const uint2*)(g_hb + (size_t)s * 64 + lane * 2);
            float2 f0 = __bfloat1622float2(*reinterpret_cast<__nv_bfloat162*>(&v.x));
            float2 f1 = __bfloat1622float2(*reinterpret_cast<__nv_bfloat162*>(&v.y));
            a0.x += f0.x; a0.y += f0.y; a0.z += f1.x; a0.w += f1.y;
        }
        float cd = g_c_dst[gw];
        float cs = rsqrtf((float)max(g_outdeg[gw], 1));
        float wn = g_w[gw] * cs;
        vloc.x = fmaf(fmaxf(fmaf(a0.x + a1.x, cd, bb.x), 0.0f), wn, vloc.x);
        vloc.y = fmaf(fmaxf(fmaf(a0.y + a1.y, cd, bb.y), 0.0f), wn, vloc.y);
        vloc.z = fmaf(fmaxf(fmaf(a0.z + a1.z, cd, bb.z), 0.0f), wn, vloc.z);
        vloc.w = fmaf(fmaxf(fmaf(a0.w + a1.w, cd, bb.w), 0.0f), wn, vloc.w);
    }

    *(float4*)&sv[wid][lane * 4] = vloc;
    __syncthreads();
    if (tid < HID_F) {
        float s = 0.0f;
#pragma unroll
        for (int w = 0; w < 8; w++) s += sv[w][tid];
        atomicAdd(&g_vacc[tid], s);
    }
}

// out = (g_vacc @ W2) / N + b2   -> [1, 64]
__global__ void k_final(const float* __restrict__ W2, const float* __restrict__ b2,
                        float* __restrict__ out) {
    __shared__ float v[HID_F];
    int tid = threadIdx.x;
    if (tid < HID_F) v[tid] = g_vacc[tid];
    __syncthreads();
    if (tid < OUT_F) {
        float s = 0.0f;
#pragma unroll 8
        for (int k = 0; k < HID_F; k++) s = fmaf(v[k], W2[k * OUT_F + tid], s);
        out[tid] = s * (1.0f / (float)NN) + b2[tid];
    }
}

// ---------------- launch ----------------
extern "C" void kernel_launch(void* const* d_in, const int* in_sizes, int n_in,
                              void* d_out, int out_size) {
    const float* feat = (const float*)d_in[0];
    const int*   src  = (const int*)d_in[1];
    const int*   dst  = (const int*)d_in[2];
    const float* W1   = (const float*)d_in[3];
    const float* b1   = (const float*)d_in[4];
    const float* W2   = (const float*)d_in[5];
    const float* b2   = (const float*)d_in[6];
    float* out = (float*)d_out;

    (void)in_sizes; (void)n_in; (void)out_size;

    cudaFuncSetAttribute(k_gemm_mma, cudaFuncAttributeMaxDynamicSharedMemorySize, SM_GEMM_TOTAL);

    k_zero<<<256, 256>>>();

    // Fork after zero: branch A (s2) = outdeg -> GEMM ; branch B (default) = indeg -> CSR.
    cudaEventRecord(g_ctx.ev_fork, 0);
    cudaStreamWaitEvent(g_ctx.s2, g_ctx.ev_fork, 0);
    k_deg_out<<<1024, 256, 0, g_ctx.s2>>>(src);
    k_gemm_mma<<<(NN + 127) / 128, 256, SM_GEMM_TOTAL, g_ctx.s2>>>(feat, W1);
    cudaEventRecord(g_ctx.ev_join, g_ctx.s2);

    k_deg_in<<<1024, 256>>>(dst);
    k_scan1<<<NB_SCAN, 1024>>>();
    k_scan3<<<NB_SCAN, 1024>>>();
    k_scatter_wsum<<<1024, 256>>>(src, dst);

    // Join before SpMM (needs g_hb + outdeg from s2, CSR/w/c_dst from default).
    cudaStreamWaitEvent(0, g_ctx.ev_join, 0);
    k_spmm_vacc<<<SPMM_GRID, 256>>>(b1);
    k_final<<<1, 128>>>(W2, b2, out);
}